// round 1
// baseline (speedup 1.0000x reference)
#include <cuda_runtime.h>
#include <math.h>

#define HH 128
#define WW 128
#define BATCH 8
#define CCH 128

// -------- scratch (device globals: no allocation allowed) --------
__device__ float g_cost[(size_t)BATCH*HH*WW*81];   // 42.5 MB
__device__ float g_bufA[(size_t)BATCH*HH*WW*128];  // 67 MB
__device__ float g_bufB[(size_t)BATCH*HH*WW*128];  // 67 MB

__device__ __forceinline__ float mish_f(float v) {
    float sp = (v > 20.f) ? v : log1pf(expf(v));
    return v * tanhf(sp);
}

// ================= cost volume =================
// tile: 16 rows x 8 cols of pixels per block; 288 threads.
// smem: nxt halo 24 rows x 16 cols x 128 ch, padded strides for bank-conflict-free LDS.128
#define CT_COLS 132                 // col stride (floats)
#define CT_RS   2116                // row stride (floats): 16*132 + 4  (== 4 mod 32)
#define CT_SMEM (CT_RS * 24 * 4)    // 203,136 B

__global__ void cost_kernel(const float* __restrict__ prv,
                            const float* __restrict__ nxt,
                            float* __restrict__ cost)
{
    extern __shared__ float sm[];
    const int b  = blockIdx.z;
    const int y0 = blockIdx.y * 16;
    const int x0 = blockIdx.x * 8;
    const int tid = threadIdx.x;

    // load nxt halo (24 x 16 x 128), zero-padded OOB
    for (int idx = tid; idx < 24 * 16 * 32; idx += 288) {
        int row = idx >> 9;            // /512
        int col = (idx >> 5) & 15;
        int c4  = idx & 31;
        int gy = y0 - 4 + row;
        int gx = x0 - 4 + col;
        float4 v = make_float4(0.f, 0.f, 0.f, 0.f);
        if (gy >= 0 && gy < HH && gx >= 0 && gx < WW)
            v = *(const float4*)(nxt + (((size_t)b*HH + gy)*WW + gx)*CCH + c4*4);
        *(float4*)(sm + row*CT_RS + col*CT_COLS + c4*4) = v;
    }
    __syncthreads();

    // 288 tasks: (r in [0,16), q in [0,2) -> 4-px x-quad, di in [0,9)); di fastest in warp
    const int r  = tid / 18;
    const int q  = (tid % 18) / 9;
    const int di = tid % 9;
    const int xs = q * 4;

    float acc[36];
    #pragma unroll
    for (int k = 0; k < 36; k++) acc[k] = 0.f;

    const float* prow = prv + (((size_t)b*HH + (y0 + r))*WW + (x0 + xs))*CCH;
    const float* nbase = sm + (r + di)*CT_RS + xs*CT_COLS;

    for (int c4 = 0; c4 < 32; c4++) {
        float4 nv[12];
        #pragma unroll
        for (int m = 0; m < 12; m++)
            nv[m] = *(const float4*)(nbase + m*CT_COLS + c4*4);
        #pragma unroll
        for (int i = 0; i < 4; i++) {
            float4 p = *(const float4*)(prow + (size_t)i*CCH + c4*4);
            #pragma unroll
            for (int dj = 0; dj < 9; dj++) {
                float4 nn = nv[i + dj];
                acc[i*9 + dj] += p.x*nn.x + p.y*nn.y + p.z*nn.z + p.w*nn.w;
            }
        }
    }

    const float inv = 1.0f / 128.0f;
    #pragma unroll
    for (int i = 0; i < 4; i++) {
        size_t base = (((size_t)b*HH + (y0 + r))*WW + (x0 + xs + i))*81 + di*9;
        #pragma unroll
        for (int dj = 0; dj < 9; dj++)
            cost[base + dj] = acc[i*9 + dj] * inv;
    }
}

// ================= fused sep-conv layer =================
// block: 128 threads, tile = 8x8 pixels. Phase A: depthwise 3x3 -> smem.
// Phase B: GEMM 64xCOUT = dwtile(64 x CINP) @ pw(CIN x COUT), bias + mish.
template<int CIN, int CINP, int COUT, int TN, bool L0>
__global__ void layer_kernel(const float* __restrict__ in,
                             const float* __restrict__ dww,
                             const float* __restrict__ pw,
                             const float* __restrict__ bias,
                             float* __restrict__ out,
                             const float* __restrict__ cost,
                             const float* __restrict__ prv,
                             const float* __restrict__ nxt)
{
    extern __shared__ float sm[];
    float* dwt = sm;                    // [64][CINP]
    float* Bs  = sm + 64 * CINP;        // [32][COUT]

    const int b  = blockIdx.z;
    const int y0 = blockIdx.y * 8;
    const int x0 = blockIdx.x * 8;
    const int tid = threadIdx.x;

    // ---- Phase A: depthwise 3x3 (zero-pad SAME), write [px][c] into smem ----
    for (int idx = tid; idx < 64 * CINP; idx += 128) {
        int px = idx / CINP;
        int c  = idx - px * CINP;
        float v = 0.f;
        if (c < CIN) {
            int y = y0 + (px >> 3);
            int x = x0 + (px & 7);
            #pragma unroll
            for (int t = 0; t < 9; t++) {
                int yy = y + t/3 - 1;
                int xx = x + (t%3) - 1;
                if (yy < 0 || yy >= HH || xx < 0 || xx >= WW) continue;
                size_t pix = ((size_t)b*HH + yy)*WW + xx;
                float iv;
                if constexpr (L0) {
                    if (c < 81)        iv = cost[pix*81 + c];
                    else if (c < 209)  iv = prv[pix*128 + (c - 81)];
                    else               iv = nxt[pix*128 + (c - 209)];
                } else {
                    iv = in[pix*CIN + c];
                }
                v += dww[t*CIN + c] * iv;
            }
        }
        dwt[px * CINP + c] = v;
    }

    // ---- Phase B: pointwise GEMM ----
    const int cx = tid & 15;   // 16 cout groups of TN
    const int ry = tid >> 4;   // 8 pixel groups of 8

    float acc[8][TN];
    #pragma unroll
    for (int i = 0; i < 8; i++)
        #pragma unroll
        for (int j = 0; j < TN; j++) acc[i][j] = 0.f;

    for (int k0 = 0; k0 < CINP; k0 += 32) {
        __syncthreads();
        for (int j = tid; j < 32 * COUT; j += 128) {
            int kk = j / COUT;
            int co = j - kk * COUT;
            int kg = k0 + kk;
            Bs[j] = (kg < CIN) ? pw[(size_t)kg * COUT + co] : 0.f;
        }
        __syncthreads();
        #pragma unroll
        for (int kk = 0; kk < 32; kk++) {
            float a[8];
            #pragma unroll
            for (int i = 0; i < 8; i++)
                a[i] = dwt[(ry*8 + i)*CINP + k0 + kk];
            float bv[TN];
            #pragma unroll
            for (int j = 0; j < TN; j++)
                bv[j] = Bs[kk*COUT + cx*TN + j];
            #pragma unroll
            for (int i = 0; i < 8; i++)
                #pragma unroll
                for (int j = 0; j < TN; j++)
                    acc[i][j] = fmaf(a[i], bv[j], acc[i][j]);
        }
    }

    // ---- epilogue: bias + mish ----
    #pragma unroll
    for (int i = 0; i < 8; i++) {
        int px = ry*8 + i;
        int y = y0 + (px >> 3);
        int x = x0 + (px & 7);
        size_t base = (((size_t)b*HH + y)*WW + x)*COUT + cx*TN;
        #pragma unroll
        for (int j = 0; j < TN; j++) {
            float v = acc[i][j] + bias[cx*TN + j];
            out[base + j] = mish_f(v);
        }
    }
}

// ================= final flow head (32 -> 2, no bias, no act) =================
__global__ void layer5_kernel(const float* __restrict__ in,
                              const float* __restrict__ dww,
                              const float* __restrict__ pw,
                              float* __restrict__ out)
{
    int pix = blockIdx.x * blockDim.x + threadIdx.x;
    if (pix >= BATCH*HH*WW) return;
    int b = pix / (HH*WW);
    int rem = pix % (HH*WW);
    int y = rem / WW, x = rem % WW;

    float dwv[32];
    #pragma unroll
    for (int c = 0; c < 32; c++) dwv[c] = 0.f;

    #pragma unroll
    for (int t = 0; t < 9; t++) {
        int yy = y + t/3 - 1;
        int xx = x + (t%3) - 1;
        if (yy < 0 || yy >= HH || xx < 0 || xx >= WW) continue;
        const float4* ip = (const float4*)(in + (((size_t)b*HH + yy)*WW + xx)*32);
        #pragma unroll
        for (int c4 = 0; c4 < 8; c4++) {
            float4 v = ip[c4];
            float4 w = *(const float4*)(dww + t*32 + c4*4);
            dwv[c4*4 + 0] += w.x * v.x;
            dwv[c4*4 + 1] += w.y * v.y;
            dwv[c4*4 + 2] += w.z * v.z;
            dwv[c4*4 + 3] += w.w * v.w;
        }
    }

    float o0 = 0.f, o1 = 0.f;
    #pragma unroll
    for (int c = 0; c < 32; c++) {
        o0 += dwv[c] * pw[c*2 + 0];
        o1 += dwv[c] * pw[c*2 + 1];
    }
    float2 r; r.x = o0; r.y = o1;
    *(float2*)(out + (size_t)pix*2) = r;
}

// ================= host launch =================
extern "C" void kernel_launch(void* const* d_in, const int* in_sizes, int n_in,
                              void* d_out, int out_size)
{
    const float* prv = (const float*)d_in[0];
    const float* nxt = (const float*)d_in[1];
    const float* dw0 = (const float*)d_in[2];
    const float* pw0 = (const float*)d_in[3];
    const float* b0  = (const float*)d_in[4];
    const float* dw1 = (const float*)d_in[5];
    const float* pw1 = (const float*)d_in[6];
    const float* b1  = (const float*)d_in[7];
    const float* dw2 = (const float*)d_in[8];
    const float* pw2 = (const float*)d_in[9];
    const float* b2  = (const float*)d_in[10];
    const float* dw3 = (const float*)d_in[11];
    const float* pw3 = (const float*)d_in[12];
    const float* b3  = (const float*)d_in[13];
    const float* dw4 = (const float*)d_in[14];
    const float* pw4 = (const float*)d_in[15];
    const float* b4  = (const float*)d_in[16];
    const float* dw5 = (const float*)d_in[17];
    const float* pw5 = (const float*)d_in[18];
    float* out = (float*)d_out;

    float *cost, *bufA, *bufB;
    cudaGetSymbolAddress((void**)&cost, g_cost);
    cudaGetSymbolAddress((void**)&bufA, g_bufA);
    cudaGetSymbolAddress((void**)&bufB, g_bufB);

    const int S0 = (64*352 + 32*128) * 4;  // 106496
    const int S1 = (64*128 + 32*128) * 4;  // 49152
    const int S2 = (64*128 + 32*96 ) * 4;  // 45056
    const int S3 = (64*96  + 32*64 ) * 4;  // 32768
    const int S4 = (64*64  + 32*32 ) * 4;  // 20480

    cudaFuncSetAttribute(cost_kernel, cudaFuncAttributeMaxDynamicSharedMemorySize, CT_SMEM);
    cudaFuncSetAttribute((const void*)layer_kernel<337,352,128,8,true >, cudaFuncAttributeMaxDynamicSharedMemorySize, S0);
    cudaFuncSetAttribute((const void*)layer_kernel<128,128,128,8,false>, cudaFuncAttributeMaxDynamicSharedMemorySize, S1);
    cudaFuncSetAttribute((const void*)layer_kernel<128,128, 96,6,false>, cudaFuncAttributeMaxDynamicSharedMemorySize, S2);
    cudaFuncSetAttribute((const void*)layer_kernel< 96, 96, 64,4,false>, cudaFuncAttributeMaxDynamicSharedMemorySize, S3);
    cudaFuncSetAttribute((const void*)layer_kernel< 64, 64, 32,2,false>, cudaFuncAttributeMaxDynamicSharedMemorySize, S4);

    dim3 cgrid(16, 8, BATCH);                 // 8-wide x 16-tall tiles
    cost_kernel<<<cgrid, 288, CT_SMEM>>>(prv, nxt, cost);

    dim3 lgrid(16, 16, BATCH);                // 8x8 tiles
    layer_kernel<337,352,128,8,true ><<<lgrid, 128, S0>>>(nullptr, dw0, pw0, b0, bufA, cost, prv, nxt);
    layer_kernel<128,128,128,8,false><<<lgrid, 128, S1>>>(bufA, dw1, pw1, b1, bufB, nullptr, nullptr, nullptr);
    layer_kernel<128,128, 96,6,false><<<lgrid, 128, S2>>>(bufB, dw2, pw2, b2, bufA, nullptr, nullptr, nullptr);
    layer_kernel< 96, 96, 64,4,false><<<lgrid, 128, S3>>>(bufA, dw3, pw3, b3, bufB, nullptr, nullptr, nullptr);
    layer_kernel< 64, 64, 32,2,false><<<lgrid, 128, S4>>>(bufB, dw4, pw4, b4, bufA, nullptr, nullptr, nullptr);

    layer5_kernel<<<(BATCH*HH*WW + 255)/256, 256>>>(bufA, dw5, pw5, out);
}

// round 2
// speedup vs baseline: 3.0898x; 3.0898x over previous
#include <cuda_runtime.h>
#include <math.h>

#define HH 128
#define WW 128
#define BATCH 8
#define NPIX (BATCH*HH*WW)

// x0 layout per pixel: [prv(128) | nxt(128) | cost(81) | pad(15)] = 352 ch
// weight-channel remap (buffer->original concat [cost,prv,nxt]):
//   cb < 256  -> cb + 81   (prv/nxt region)
//   cb < 337  -> cb - 256  (cost region)
//   else invalid (zero)
__device__ float g_x0  [(size_t)NPIX*352];   // 184 MB (zero-init pad stays zero)
__device__ float g_bufA[(size_t)NPIX*128];
__device__ float g_bufB[(size_t)NPIX*128];

__device__ __forceinline__ float mish_f(float v) {
    if (v > 20.f) return v;
    float u = __expf(v);
    float w = u * (u + 2.f);
    return v * __fdividef(w, w + 2.f);
}

// ================= concat copy: prv/nxt -> x0 =================
__global__ void concat_kernel(const float4* __restrict__ prv,
                              const float4* __restrict__ nxt,
                              float4* __restrict__ x0)
{
    int i = blockIdx.x * 256 + threadIdx.x;       // NPIX*64 total
    int pix = i >> 6, q = i & 63;
    float4 v = (q < 32) ? prv[pix*32 + q] : nxt[pix*32 + (q - 32)];
    x0[(size_t)pix*88 + q] = v;
}

// ================= cost volume (channel-chunked halo) =================
#define CCS 36
#define CRS 580    // 16*36 + 4
__global__ void __launch_bounds__(288, 2)
cost_kernel(const float* __restrict__ prv, const float* __restrict__ nxt,
            float* __restrict__ x0)
{
    extern __shared__ __align__(16) float sm[];   // 24*CRS floats = 55680 B
    const int b  = blockIdx.z;
    const int y0 = blockIdx.y * 16;
    const int xb = blockIdx.x * 8;
    const int tid = threadIdx.x;
    const int r  = tid / 18;
    const int q  = (tid % 18) / 9;
    const int di = tid % 9;
    const int xs = q * 4;

    float acc[36];
    #pragma unroll
    for (int k = 0; k < 36; k++) acc[k] = 0.f;

    for (int cc = 0; cc < 4; cc++) {
        if (cc) __syncthreads();
        // halo: 24 x 16 x 8 quads
        for (int idx = tid; idx < 3072; idx += 288) {
            int c4 = idx & 7, col = (idx >> 3) & 15, row = idx >> 7;
            int gy = y0 - 4 + row, gx = xb - 4 + col;
            float4 v = make_float4(0.f,0.f,0.f,0.f);
            if (gy >= 0 && gy < HH && gx >= 0 && gx < WW)
                v = ((const float4*)nxt)[((b*HH+gy)*WW+gx)*32 + cc*8 + c4];
            *(float4*)(sm + row*CRS + col*CCS + c4*4) = v;
        }
        __syncthreads();

        const float* nbase = sm + (r + di)*CRS + xs*CCS;
        const float4* prow = (const float4*)prv + (size_t)((b*HH + y0 + r)*WW + xb + xs)*32 + cc*8;

        #pragma unroll 2
        for (int c4 = 0; c4 < 8; c4++) {
            float4 nv[12];
            #pragma unroll
            for (int m = 0; m < 12; m++)
                nv[m] = *(const float4*)(nbase + m*CCS + c4*4);
            #pragma unroll
            for (int i = 0; i < 4; i++) {
                float4 p = prow[i*32 + c4];
                #pragma unroll
                for (int dj = 0; dj < 9; dj++) {
                    float4 nn = nv[i + dj];
                    float s = acc[i*9+dj];
                    s = fmaf(p.x, nn.x, s); s = fmaf(p.y, nn.y, s);
                    s = fmaf(p.z, nn.z, s); s = fmaf(p.w, nn.w, s);
                    acc[i*9+dj] = s;
                }
            }
        }
    }

    const float inv = 1.0f / 128.0f;
    #pragma unroll
    for (int i = 0; i < 4; i++) {
        size_t base = (size_t)((b*HH + y0 + r)*WW + xb + xs + i)*352 + 256 + di*9;
        #pragma unroll
        for (int dj = 0; dj < 9; dj++)
            x0[base + dj] = acc[i*9+dj] * inv;
    }
}

// ================= fused sep-conv layer =================
// 256 threads, tile 16x8 = 128 px. K-chunks of 32 channels:
//   halo(18x10x32) -> depthwise -> dwt[k][px] (transposed) -> GEMM accumulate.
template<int CIN, int CINB, int COUT, int TN, bool L0M>
__global__ void __launch_bounds__(256, 2)
layer_kernel(const float* __restrict__ in, const float* __restrict__ dww,
             const float* __restrict__ pw, const float* __restrict__ bias,
             float* __restrict__ out)
{
    constexpr int CXN = COUT / TN;
    constexpr int RYN = 256 / CXN;
    constexpr int TM  = 128 / RYN;
    constexpr int KCH = CINB / 32;

    extern __shared__ __align__(16) float sm[];
    float* halo = sm;                       // 180*32   = 5760
    float* dwt  = sm + 5760;                // 32*133   = 4256
    float* Bsm  = sm + 10016;               // 32*COUT
    float* sdw  = sm + 10016 + 32*COUT;     // 9*32     = 288

    const int b  = blockIdx.z;
    const int ty = blockIdx.y * 16;
    const int tx = blockIdx.x * 8;
    const int tid = threadIdx.x;
    const int cx = tid % CXN;
    const int ry = tid / CXN;

    float acc[TM][TN];
    #pragma unroll
    for (int i = 0; i < TM; i++)
        #pragma unroll
        for (int j = 0; j < TN; j++) acc[i][j] = 0.f;

    for (int kc = 0; kc < KCH; kc++) {
        const int k0 = kc * 32;
        if (kc) __syncthreads();

        // B chunk [32][COUT]
        for (int j = tid; j < 32*COUT; j += 256) {
            int kk = j / COUT, co = j - kk*COUT;
            int cb = k0 + kk;
            int corig = L0M ? (cb < 256 ? cb + 81 : cb - 256) : cb;
            bool valid = L0M ? (cb < 337) : true;
            Bsm[j] = valid ? pw[corig*COUT + co] : 0.f;
        }
        // depthwise weights chunk [9][32]
        for (int j = tid; j < 288; j += 256) {
            int t = j >> 5, c = j & 31;
            int cb = k0 + c;
            int corig = L0M ? (cb < 256 ? cb + 81 : cb - 256) : cb;
            bool valid = L0M ? (cb < 337) : true;
            sdw[j] = valid ? dww[t*CIN + corig] : 0.f;
        }
        // input halo chunk 18x10 px x 8 quads
        for (int idx = tid; idx < 1440; idx += 256) {
            int c4 = idx & 7, p = idx >> 3;
            int hy = p / 10, hx = p - hy*10;
            int gy = ty - 1 + hy, gx = tx - 1 + hx;
            float4 v = make_float4(0.f,0.f,0.f,0.f);
            if (gy >= 0 && gy < HH && gx >= 0 && gx < WW)
                v = ((const float4*)in)[(size_t)((b*HH+gy)*WW+gx)*(CINB/4) + kc*8 + c4];
            *(float4*)(halo + p*32 + c4*4) = v;
        }
        __syncthreads();

        // depthwise 3x3 -> transposed dwt[k][px]
        for (int task = tid; task < 1024; task += 256) {
            int c4 = task & 7, px = task >> 3;
            int y = px >> 3, x = px & 7;
            float4 v = make_float4(0.f,0.f,0.f,0.f);
            #pragma unroll
            for (int t = 0; t < 9; t++) {
                int hp = (y + t/3)*10 + (x + t%3);
                float4 h = *(const float4*)(halo + hp*32 + c4*4);
                float4 w = *(const float4*)(sdw  + t*32  + c4*4);
                v.x = fmaf(w.x, h.x, v.x);
                v.y = fmaf(w.y, h.y, v.y);
                v.z = fmaf(w.z, h.z, v.z);
                v.w = fmaf(w.w, h.w, v.w);
            }
            int cb = c4 * 4;
            dwt[(cb+0)*133 + px] = v.x;
            dwt[(cb+1)*133 + px] = v.y;
            dwt[(cb+2)*133 + px] = v.z;
            dwt[(cb+3)*133 + px] = v.w;
        }
        __syncthreads();

        // GEMM: acc[TM][TN] += dwt^T @ B
        #pragma unroll 4
        for (int kk = 0; kk < 32; kk++) {
            float a[TM];
            #pragma unroll
            for (int i = 0; i < TM; i++)
                a[i] = dwt[kk*133 + ry*TM + i];
            float bv[TN];
            if constexpr (TN == 8) {
                float4 b0 = *(const float4*)(Bsm + kk*COUT + cx*8);
                float4 b1 = *(const float4*)(Bsm + kk*COUT + cx*8 + 4);
                bv[0]=b0.x; bv[1]=b0.y; bv[2]=b0.z; bv[3]=b0.w;
                bv[4]=b1.x; bv[5]=b1.y; bv[6]=b1.z; bv[7]=b1.w;
            } else if constexpr (TN == 4) {
                float4 b0 = *(const float4*)(Bsm + kk*COUT + cx*4);
                bv[0]=b0.x; bv[1]=b0.y; bv[2]=b0.z; bv[3]=b0.w;
            } else {
                #pragma unroll
                for (int j = 0; j < TN; j++)
                    bv[j] = Bsm[kk*COUT + cx*TN + j];
            }
            #pragma unroll
            for (int i = 0; i < TM; i++)
                #pragma unroll
                for (int j = 0; j < TN; j++)
                    acc[i][j] = fmaf(a[i], bv[j], acc[i][j]);
        }
    }

    // epilogue: bias + mish
    float bb[TN];
    #pragma unroll
    for (int j = 0; j < TN; j++) bb[j] = bias[cx*TN + j];

    #pragma unroll
    for (int i = 0; i < TM; i++) {
        int px = ry*TM + i;
        int y = ty + (px >> 3), x = tx + (px & 7);
        float* op = out + (size_t)((b*HH+y)*WW + x)*COUT + cx*TN;
        if constexpr (TN % 4 == 0) {
            #pragma unroll
            for (int j0 = 0; j0 < TN; j0 += 4) {
                float4 o;
                o.x = mish_f(acc[i][j0+0] + bb[j0+0]);
                o.y = mish_f(acc[i][j0+1] + bb[j0+1]);
                o.z = mish_f(acc[i][j0+2] + bb[j0+2]);
                o.w = mish_f(acc[i][j0+3] + bb[j0+3]);
                *(float4*)(op + j0) = o;
            }
        } else {
            #pragma unroll
            for (int j = 0; j < TN; j++)
                op[j] = mish_f(acc[i][j] + bb[j]);
        }
    }
}

// ================= final flow head (32 -> 2, no bias/act) =================
__global__ void layer5_kernel(const float* __restrict__ in,
                              const float* __restrict__ dww,
                              const float* __restrict__ pw,
                              float* __restrict__ out)
{
    __shared__ __align__(16) float halo[180*36];   // px stride 36 (bank spread)
    __shared__ __align__(16) float wsm[288 + 64];

    const int b  = blockIdx.z;
    const int ty = blockIdx.y * 16;
    const int tx = blockIdx.x * 8;
    const int tid = threadIdx.x;   // 128

    for (int j = tid; j < 288; j += 128) wsm[j] = dww[j];
    if (tid < 64) wsm[288 + tid] = pw[tid];

    for (int idx = tid; idx < 1440; idx += 128) {
        int c4 = idx & 7, p = idx >> 3;
        int hy = p / 10, hx = p - hy*10;
        int gy = ty - 1 + hy, gx = tx - 1 + hx;
        float4 v = make_float4(0.f,0.f,0.f,0.f);
        if (gy >= 0 && gy < HH && gx >= 0 && gx < WW)
            v = ((const float4*)in)[(size_t)((b*HH+gy)*WW+gx)*8 + c4];
        *(float4*)(halo + p*36 + c4*4) = v;
    }
    __syncthreads();

    int y = tid >> 3, x = tid & 7;
    float dwv[32];
    #pragma unroll
    for (int c = 0; c < 32; c++) dwv[c] = 0.f;

    #pragma unroll
    for (int t = 0; t < 9; t++) {
        int hp = (y + t/3)*36 + (x + t%3)*36 - (y + t/3)*36;  // placeholder avoided below
        hp = ((y + t/3)*10 + (x + t%3))*36;
        #pragma unroll
        for (int c4 = 0; c4 < 8; c4++) {
            float4 h = *(const float4*)(halo + hp + c4*4);
            float4 w = *(const float4*)(wsm + t*32 + c4*4);
            dwv[c4*4+0] = fmaf(w.x, h.x, dwv[c4*4+0]);
            dwv[c4*4+1] = fmaf(w.y, h.y, dwv[c4*4+1]);
            dwv[c4*4+2] = fmaf(w.z, h.z, dwv[c4*4+2]);
            dwv[c4*4+3] = fmaf(w.w, h.w, dwv[c4*4+3]);
        }
    }

    float o0 = 0.f, o1 = 0.f;
    #pragma unroll
    for (int c = 0; c < 32; c++) {
        o0 = fmaf(dwv[c], wsm[288 + c*2 + 0], o0);
        o1 = fmaf(dwv[c], wsm[288 + c*2 + 1], o1);
    }
    int pix = (b*HH + ty + y)*WW + tx + x;
    float2 r; r.x = o0; r.y = o1;
    *(float2*)(out + (size_t)pix*2) = r;
}

// ================= host launch =================
extern "C" void kernel_launch(void* const* d_in, const int* in_sizes, int n_in,
                              void* d_out, int out_size)
{
    const float* prv = (const float*)d_in[0];
    const float* nxt = (const float*)d_in[1];
    const float* dw0 = (const float*)d_in[2];
    const float* pw0 = (const float*)d_in[3];
    const float* b0  = (const float*)d_in[4];
    const float* dw1 = (const float*)d_in[5];
    const float* pw1 = (const float*)d_in[6];
    const float* b1  = (const float*)d_in[7];
    const float* dw2 = (const float*)d_in[8];
    const float* pw2 = (const float*)d_in[9];
    const float* b2  = (const float*)d_in[10];
    const float* dw3 = (const float*)d_in[11];
    const float* pw3 = (const float*)d_in[12];
    const float* b3  = (const float*)d_in[13];
    const float* dw4 = (const float*)d_in[14];
    const float* pw4 = (const float*)d_in[15];
    const float* b4  = (const float*)d_in[16];
    const float* dw5 = (const float*)d_in[17];
    const float* pw5 = (const float*)d_in[18];
    float* out = (float*)d_out;

    float *x0, *bufA, *bufB;
    cudaGetSymbolAddress((void**)&x0,   g_x0);
    cudaGetSymbolAddress((void**)&bufA, g_bufA);
    cudaGetSymbolAddress((void**)&bufB, g_bufB);

    const int SC  = 24*CRS*4;                       // 55680
    const int SL0 = (10304 + 32*128)*4;             // 57600
    const int SL1 = SL0;
    const int SL2 = (10304 + 32*96 )*4;             // 53504
    const int SL3 = (10304 + 32*64 )*4;             // 49408
    const int SL4 = (10304 + 32*32 )*4;             // 45312

    cudaFuncSetAttribute(cost_kernel, cudaFuncAttributeMaxDynamicSharedMemorySize, SC);
    cudaFuncSetAttribute((const void*)layer_kernel<337,352,128,8,true >, cudaFuncAttributeMaxDynamicSharedMemorySize, SL0);
    cudaFuncSetAttribute((const void*)layer_kernel<128,128,128,8,false>, cudaFuncAttributeMaxDynamicSharedMemorySize, SL1);
    cudaFuncSetAttribute((const void*)layer_kernel<128,128, 96,6,false>, cudaFuncAttributeMaxDynamicSharedMemorySize, SL2);
    cudaFuncSetAttribute((const void*)layer_kernel< 96, 96, 64,8,false>, cudaFuncAttributeMaxDynamicSharedMemorySize, SL3);
    cudaFuncSetAttribute((const void*)layer_kernel< 64, 64, 32,4,false>, cudaFuncAttributeMaxDynamicSharedMemorySize, SL4);

    concat_kernel<<<NPIX*64/256, 256>>>((const float4*)prv, (const float4*)nxt, (float4*)x0);

    dim3 cgrid(16, 8, BATCH);
    cost_kernel<<<cgrid, 288, SC>>>(prv, nxt, x0);

    dim3 lgrid(16, 8, BATCH);
    layer_kernel<337,352,128,8,true ><<<lgrid, 256, SL0>>>(x0,   dw0, pw0, b0, bufA);
    layer_kernel<128,128,128,8,false><<<lgrid, 256, SL1>>>(bufA, dw1, pw1, b1, bufB);
    layer_kernel<128,128, 96,6,false><<<lgrid, 256, SL2>>>(bufB, dw2, pw2, b2, bufA);
    layer_kernel< 96, 96, 64,8,false><<<lgrid, 256, SL3>>>(bufA, dw3, pw3, b3, bufB);
    layer_kernel< 64, 64, 32,4,false><<<lgrid, 256, SL4>>>(bufB, dw4, pw4, b4, bufA);

    layer5_kernel<<<lgrid, 128>>>(bufA, dw5, pw5, out);
}

// round 4
// speedup vs baseline: 4.3479x; 1.4072x over previous
#include <cuda_runtime.h>
#include <math.h>
#include <stdint.h>

#define HH 128
#define WW 128
#define BATCH 8
#define NPIX (BATCH*HH*WW)

// x0 layout per pixel: [prv(128) | nxt(128) | cost(81) | pad(15)] = 352 ch
__device__ float g_x0  [(size_t)NPIX*352];
__device__ float g_bufA[(size_t)NPIX*128];
__device__ float g_bufB[(size_t)NPIX*128];

__device__ __forceinline__ float mish_f(float v) {
    if (v > 20.f) return v;
    float u = __expf(v);
    float w = u * (u + 2.f);
    return v * __fdividef(w, w + 2.f);
}

__device__ __forceinline__ uint32_t f2tf32(float x) {
    uint32_t r;
    asm("cvt.rna.tf32.f32 %0, %1;" : "=r"(r) : "f"(x));
    return r;
}

__device__ __forceinline__ void mma_tf32(float acc[4],
                                         uint32_t a0, uint32_t a1, uint32_t a2, uint32_t a3,
                                         uint32_t b0, uint32_t b1) {
    asm volatile(
        "mma.sync.aligned.m16n8k8.row.col.f32.tf32.tf32.f32 "
        "{%0,%1,%2,%3}, {%4,%5,%6,%7}, {%8,%9}, {%0,%1,%2,%3};"
        : "+f"(acc[0]), "+f"(acc[1]), "+f"(acc[2]), "+f"(acc[3])
        : "r"(a0), "r"(a1), "r"(a2), "r"(a3), "r"(b0), "r"(b1));
}

// ================= concat copy: prv/nxt -> x0 =================
__global__ void concat_kernel(const float4* __restrict__ prv,
                              const float4* __restrict__ nxt,
                              float4* __restrict__ x0)
{
    int i = blockIdx.x * 256 + threadIdx.x;
    int pix = i >> 6, q = i & 63;
    float4 v = (q < 32) ? prv[pix*32 + q] : nxt[pix*32 + (q - 32)];
    x0[(size_t)pix*88 + q] = v;
}

// ================= cost volume =================
#define CCS 36
#define CRS 580
__global__ void __launch_bounds__(288, 2)
cost_kernel(const float* __restrict__ prv, const float* __restrict__ nxt,
            float* __restrict__ x0)
{
    extern __shared__ __align__(16) float sm[];
    const int b  = blockIdx.z;
    const int y0 = blockIdx.y * 16;
    const int xb = blockIdx.x * 8;
    const int tid = threadIdx.x;
    const int r  = tid / 18;
    const int q  = (tid % 18) / 9;
    const int di = tid % 9;
    const int xs = q * 4;

    float acc[36];
    #pragma unroll
    for (int k = 0; k < 36; k++) acc[k] = 0.f;

    for (int cc = 0; cc < 4; cc++) {
        if (cc) __syncthreads();
        for (int idx = tid; idx < 3072; idx += 288) {
            int c4 = idx & 7, col = (idx >> 3) & 15, row = idx >> 7;
            int gy = y0 - 4 + row, gx = xb - 4 + col;
            float4 v = make_float4(0.f,0.f,0.f,0.f);
            if (gy >= 0 && gy < HH && gx >= 0 && gx < WW)
                v = ((const float4*)nxt)[((b*HH+gy)*WW+gx)*32 + cc*8 + c4];
            *(float4*)(sm + row*CRS + col*CCS + c4*4) = v;
        }
        __syncthreads();

        const float* nbase = sm + (r + di)*CRS + xs*CCS;
        const float4* prow = (const float4*)prv + (size_t)((b*HH + y0 + r)*WW + xb + xs)*32 + cc*8;

        #pragma unroll 2
        for (int c4 = 0; c4 < 8; c4++) {
            float4 nv[12];
            #pragma unroll
            for (int m = 0; m < 12; m++)
                nv[m] = *(const float4*)(nbase + m*CCS + c4*4);
            #pragma unroll
            for (int i = 0; i < 4; i++) {
                float4 p = prow[i*32 + c4];
                #pragma unroll
                for (int dj = 0; dj < 9; dj++) {
                    float4 nn = nv[i + dj];
                    float s = acc[i*9+dj];
                    s = fmaf(p.x, nn.x, s); s = fmaf(p.y, nn.y, s);
                    s = fmaf(p.z, nn.z, s); s = fmaf(p.w, nn.w, s);
                    acc[i*9+dj] = s;
                }
            }
        }
    }

    const float inv = 1.0f / 128.0f;
    #pragma unroll
    for (int i = 0; i < 4; i++) {
        size_t base = (size_t)((b*HH + y0 + r)*WW + xb + xs + i)*352 + 256 + di*9;
        #pragma unroll
        for (int dj = 0; dj < 9; dj++)
            x0[base + dj] = acc[i*9+dj] * inv;
    }
}

// ================= fused sep-conv layer (mma.sync tf32) =================
// 256 threads (8 warps), tile = 16x8 = 128 px (M=128). K-chunks of 32.
// Warp w: M-rows [16w, 16w+16), full COUT. acc[COUT/8][4] in registers.
template<int CIN, int CINB, int COUT, bool L0M>
__global__ void __launch_bounds__(256, 2)
layer_mma(const float* __restrict__ in, const float* __restrict__ dww,
          const float* __restrict__ pw, const float* __restrict__ bias,
          float* __restrict__ out)
{
    constexpr int KCH = CINB / 32;
    constexpr int NT  = COUT / 8;
    constexpr int BST = COUT + 8;     // B row stride (== 8 mod 32 -> conflict-free frags)

    extern __shared__ __align__(16) float smf[];
    float* sdw   = smf;                    // 288
    float* sbias = smf + 288;              // COUT (pad 128)
    float* halo  = smf + 288 + 128;        // 5760
    uint32_t* dwt = (uint32_t*)(halo + 5760);   // 128*36 = 4608
    uint32_t* Bsm = dwt + 4608;                 // 32*BST

    const int b  = blockIdx.z;
    const int ty = blockIdx.y * 16;
    const int tx = blockIdx.x * 8;
    const int tid = threadIdx.x;
    const int lane = tid & 31;
    const int wid  = tid >> 5;
    const int kq  = lane & 3;     // k quad within kblock
    const int rr  = lane >> 2;    // row / n-col selector

    if (tid < COUT) sbias[tid] = bias[tid];

    float acc[NT][4];
    #pragma unroll
    for (int n = 0; n < NT; n++)
        #pragma unroll
        for (int j = 0; j < 4; j++) acc[n][j] = 0.f;

    for (int kc = 0; kc < KCH; kc++) {
        const int k0 = kc * 32;
        if (kc) __syncthreads();

        // ---- B chunk [32][COUT] -> tf32 smem ----
        for (int j = tid; j < 32*COUT; j += 256) {
            int kk = j / COUT, co = j - kk*COUT;
            int cb = k0 + kk;
            int corig = L0M ? (cb < 256 ? cb + 81 : cb - 256) : cb;
            bool valid = L0M ? (cb < 337) : true;
            float w = valid ? pw[(size_t)corig*COUT + co] : 0.f;
            Bsm[kk*BST + co] = f2tf32(w);
        }
        // ---- depthwise weights chunk [9][32] ----
        for (int j = tid; j < 288; j += 256) {
            int t = j >> 5, c = j & 31;
            int cb = k0 + c;
            int corig = L0M ? (cb < 256 ? cb + 81 : cb - 256) : cb;
            bool valid = L0M ? (cb < 337) : true;
            sdw[j] = valid ? dww[t*CIN + corig] : 0.f;
        }
        // ---- input halo chunk: 18x10 px x 8 quads ----
        for (int idx = tid; idx < 1440; idx += 256) {
            int c4 = idx & 7, p = idx >> 3;
            int hy = p / 10, hx = p - hy*10;
            int gy = ty - 1 + hy, gx = tx - 1 + hx;
            float4 v = make_float4(0.f,0.f,0.f,0.f);
            if (gy >= 0 && gy < HH && gx >= 0 && gx < WW)
                v = ((const float4*)in)[(size_t)((b*HH+gy)*WW+gx)*(CINB/4) + kc*8 + c4];
            *(float4*)(halo + p*32 + c4*4) = v;
        }
        __syncthreads();

        // ---- depthwise 3x3 -> dwt[px][36] (tf32 bits) ----
        for (int task = tid; task < 1024; task += 256) {
            int c4 = task & 7, px = task >> 3;
            int y = px >> 3, x = px & 7;
            float4 v = make_float4(0.f,0.f,0.f,0.f);
            #pragma unroll
            for (int t = 0; t < 9; t++) {
                int hp = (y + t/3)*10 + (x + t%3);
                float4 h = *(const float4*)(halo + hp*32 + c4*4);
                float4 w = *(const float4*)(sdw  + t*32  + c4*4);
                v.x = fmaf(w.x, h.x, v.x);
                v.y = fmaf(w.y, h.y, v.y);
                v.z = fmaf(w.z, h.z, v.z);
                v.w = fmaf(w.w, h.w, v.w);
            }
            uint4 tv;
            tv.x = f2tf32(v.x); tv.y = f2tf32(v.y);
            tv.z = f2tf32(v.z); tv.w = f2tf32(v.w);
            *(uint4*)(dwt + px*36 + c4*4) = tv;
        }
        __syncthreads();

        // ---- MMA: 4 k-blocks of 8 ----
        const uint32_t* arow0 = dwt + (wid*16 + rr)*36;
        const uint32_t* arow1 = arow0 + 8*36;
        #pragma unroll
        for (int kb = 0; kb < 4; kb++) {
            const int kof = kb*8 + kq;
            uint32_t a0 = arow0[kof];
            uint32_t a1 = arow1[kof];
            uint32_t a2 = arow0[kof + 4];
            uint32_t a3 = arow1[kof + 4];
            const uint32_t* b0p = Bsm + kof*BST + rr;
            const uint32_t* b1p = b0p + 4*BST;
            #pragma unroll
            for (int nt = 0; nt < NT; nt++) {
                uint32_t b0 = b0p[nt*8];
                uint32_t b1 = b1p[nt*8];
                mma_tf32(acc[nt], a0, a1, a2, a3, b0, b1);
            }
        }
    }

    // ---- epilogue: bias + mish, float2 stores ----
    const int px0 = wid*16 + rr;
    const int px1 = px0 + 8;
    const int y0 = ty + (px0 >> 3), x0c = tx + (px0 & 7);
    const int y1 = ty + (px1 >> 3), x1c = tx + (px1 & 7);
    float* op0 = out + (size_t)((b*HH + y0)*WW + x0c)*COUT;
    float* op1 = out + (size_t)((b*HH + y1)*WW + x1c)*COUT;

    #pragma unroll
    for (int nt = 0; nt < NT; nt++) {
        int ch = nt*8 + kq*2;
        float bb0 = sbias[ch], bb1 = sbias[ch+1];
        float2 r0, r1;
        r0.x = mish_f(acc[nt][0] + bb0);
        r0.y = mish_f(acc[nt][1] + bb1);
        r1.x = mish_f(acc[nt][2] + bb0);
        r1.y = mish_f(acc[nt][3] + bb1);
        *(float2*)(op0 + ch) = r0;
        *(float2*)(op1 + ch) = r1;
    }
}

// ================= final flow head (32 -> 2) =================
__global__ void layer5_kernel(const float* __restrict__ in,
                              const float* __restrict__ dww,
                              const float* __restrict__ pw,
                              float* __restrict__ out)
{
    __shared__ __align__(16) float halo[180*36];
    __shared__ __align__(16) float wsm[288 + 64];

    const int b  = blockIdx.z;
    const int ty = blockIdx.y * 16;
    const int tx = blockIdx.x * 8;
    const int tid = threadIdx.x;

    for (int j = tid; j < 288; j += 128) wsm[j] = dww[j];
    if (tid < 64) wsm[288 + tid] = pw[tid];

    for (int idx = tid; idx < 1440; idx += 128) {
        int c4 = idx & 7, p = idx >> 3;
        int hy = p / 10, hx = p - hy*10;
        int gy = ty - 1 + hy, gx = tx - 1 + hx;
        float4 v = make_float4(0.f,0.f,0.f,0.f);
        if (gy >= 0 && gy < HH && gx >= 0 && gx < WW)
            v = ((const float4*)in)[(size_t)((b*HH+gy)*WW+gx)*8 + c4];
        *(float4*)(halo + p*36 + c4*4) = v;
    }
    __syncthreads();

    int y = tid >> 3, x = tid & 7;
    float dwv[32];
    #pragma unroll
    for (int c = 0; c < 32; c++) dwv[c] = 0.f;

    #pragma unroll
    for (int t = 0; t < 9; t++) {
        int hp = ((y + t/3)*10 + (x + t%3))*36;
        #pragma unroll
        for (int c4 = 0; c4 < 8; c4++) {
            float4 h = *(const float4*)(halo + hp + c4*4);
            float4 w = *(const float4*)(wsm + t*32 + c4*4);
            dwv[c4*4+0] = fmaf(w.x, h.x, dwv[c4*4+0]);
            dwv[c4*4+1] = fmaf(w.y, h.y, dwv[c4*4+1]);
            dwv[c4*4+2] = fmaf(w.z, h.z, dwv[c4*4+2]);
            dwv[c4*4+3] = fmaf(w.w, h.w, dwv[c4*4+3]);
        }
    }

    float o0 = 0.f, o1 = 0.f;
    #pragma unroll
    for (int c = 0; c < 32; c++) {
        o0 = fmaf(dwv[c], wsm[288 + c*2 + 0], o0);
        o1 = fmaf(dwv[c], wsm[288 + c*2 + 1], o1);
    }
    int pix = (b*HH + ty + y)*WW + tx + x;
    float2 r; r.x = o0; r.y = o1;
    *(float2*)(out + (size_t)pix*2) = r;
}

// ================= host launch =================
extern "C" void kernel_launch(void* const* d_in, const int* in_sizes, int n_in,
                              void* d_out, int out_size)
{
    const float* prv = (const float*)d_in[0];
    const float* nxt = (const float*)d_in[1];
    const float* dw0 = (const float*)d_in[2];
    const float* pw0 = (const float*)d_in[3];
    const float* b0  = (const float*)d_in[4];
    const float* dw1 = (const float*)d_in[5];
    const float* pw1 = (const float*)d_in[6];
    const float* b1  = (const float*)d_in[7];
    const float* dw2 = (const float*)d_in[8];
    const float* pw2 = (const float*)d_in[9];
    const float* b2  = (const float*)d_in[10];
    const float* dw3 = (const float*)d_in[11];
    const float* pw3 = (const float*)d_in[12];
    const float* b3  = (const float*)d_in[13];
    const float* dw4 = (const float*)d_in[14];
    const float* pw4 = (const float*)d_in[15];
    const float* b4  = (const float*)d_in[16];
    const float* dw5 = (const float*)d_in[17];
    const float* pw5 = (const float*)d_in[18];
    float* out = (float*)d_out;

    float *x0, *bufA, *bufB;
    cudaGetSymbolAddress((void**)&x0,   g_x0);
    cudaGetSymbolAddress((void**)&bufA, g_bufA);
    cudaGetSymbolAddress((void**)&bufB, g_bufB);

    const int SC = 24*CRS*4;
    // layer smem bytes: (288 + 128 + 5760 + 4608 + 32*(COUT+8)) * 4
    const int SL128 = (288 + 128 + 5760 + 4608 + 32*136) * 4;  // 60544
    const int SL96  = (288 + 128 + 5760 + 4608 + 32*104) * 4;  // 56448
    const int SL64  = (288 + 128 + 5760 + 4608 + 32*72 ) * 4;  // 52352
    const int SL32  = (288 + 128 + 5760 + 4608 + 32*40 ) * 4;  // 48256

    cudaFuncSetAttribute(cost_kernel, cudaFuncAttributeMaxDynamicSharedMemorySize, SC);
    cudaFuncSetAttribute((const void*)layer_mma<337,352,128,true >, cudaFuncAttributeMaxDynamicSharedMemorySize, SL128);
    cudaFuncSetAttribute((const void*)layer_mma<128,128,128,false>, cudaFuncAttributeMaxDynamicSharedMemorySize, SL128);
    cudaFuncSetAttribute((const void*)layer_mma<128,128, 96,false>, cudaFuncAttributeMaxDynamicSharedMemorySize, SL96);
    cudaFuncSetAttribute((const void*)layer_mma< 96, 96, 64,false>, cudaFuncAttributeMaxDynamicSharedMemorySize, SL64);
    cudaFuncSetAttribute((const void*)layer_mma< 64, 64, 32,false>, cudaFuncAttributeMaxDynamicSharedMemorySize, SL32);

    concat_kernel<<<NPIX*64/256, 256>>>((const float4*)prv, (const float4*)nxt, (float4*)x0);

    dim3 cgrid(16, 8, BATCH);
    cost_kernel<<<cgrid, 288, SC>>>(prv, nxt, x0);

    dim3 lgrid(16, 8, BATCH);
    layer_mma<337,352,128,true ><<<lgrid, 256, SL128>>>(x0,   dw0, pw0, b0, bufA);
    layer_mma<128,128,128,false><<<lgrid, 256, SL128>>>(bufA, dw1, pw1, b1, bufB);
    layer_mma<128,128, 96,false><<<lgrid, 256, SL96 >>>(bufB, dw2, pw2, b2, bufA);
    layer_mma< 96, 96, 64,false><<<lgrid, 256, SL64 >>>(bufA, dw3, pw3, b3, bufB);
    layer_mma< 64, 64, 32,false><<<lgrid, 256, SL32 >>>(bufB, dw4, pw4, b4, bufA);

    layer5_kernel<<<lgrid, 128>>>(bufA, dw5, pw5, out);
}

// round 5
// speedup vs baseline: 4.8689x; 1.1198x over previous
#include <cuda_runtime.h>
#include <math.h>
#include <stdint.h>

#define HH 128
#define WW 128
#define BATCH 8
#define NPIX (BATCH*HH*WW)

// cost buffer: 96 channels per pixel (81 used, pad zero — never written, zero-init)
__device__ float g_cost[(size_t)NPIX*96];
__device__ float g_bufA[(size_t)NPIX*128];
__device__ float g_bufB[(size_t)NPIX*128];

__device__ __forceinline__ float mish_f(float v) {
    if (v > 20.f) return v;
    float u = __expf(v);
    float w = u * (u + 2.f);
    return v * __fdividef(w, w + 2.f);
}

__device__ __forceinline__ uint32_t f2tf32(float x) {
    uint32_t r;
    asm("cvt.rna.tf32.f32 %0, %1;" : "=r"(r) : "f"(x));
    return r;
}

__device__ __forceinline__ void mma_tf32(float acc[4],
                                         uint32_t a0, uint32_t a1, uint32_t a2, uint32_t a3,
                                         uint32_t b0, uint32_t b1) {
    asm volatile(
        "mma.sync.aligned.m16n8k8.row.col.f32.tf32.tf32.f32 "
        "{%0,%1,%2,%3}, {%4,%5,%6,%7}, {%8,%9}, {%0,%1,%2,%3};"
        : "+f"(acc[0]), "+f"(acc[1]), "+f"(acc[2]), "+f"(acc[3])
        : "r"(a0), "r"(a1), "r"(a2), "r"(a3), "r"(b0), "r"(b1));
}

// ================= cost volume =================
#define CCS 36
#define CRS 580
__global__ void __launch_bounds__(288, 2)
cost_kernel(const float* __restrict__ prv, const float* __restrict__ nxt,
            float* __restrict__ cost)
{
    extern __shared__ __align__(16) float sm[];
    const int b  = blockIdx.z;
    const int y0 = blockIdx.y * 16;
    const int xb = blockIdx.x * 8;
    const int tid = threadIdx.x;
    const int r  = tid / 18;
    const int q  = (tid % 18) / 9;
    const int di = tid % 9;
    const int xs = q * 4;

    float acc[36];
    #pragma unroll
    for (int k = 0; k < 36; k++) acc[k] = 0.f;

    for (int cc = 0; cc < 4; cc++) {
        if (cc) __syncthreads();
        for (int idx = tid; idx < 3072; idx += 288) {
            int c4 = idx & 7, col = (idx >> 3) & 15, row = idx >> 7;
            int gy = y0 - 4 + row, gx = xb - 4 + col;
            float4 v = make_float4(0.f,0.f,0.f,0.f);
            if (gy >= 0 && gy < HH && gx >= 0 && gx < WW)
                v = ((const float4*)nxt)[((b*HH+gy)*WW+gx)*32 + cc*8 + c4];
            *(float4*)(sm + row*CRS + col*CCS + c4*4) = v;
        }
        __syncthreads();

        const float* nbase = sm + (r + di)*CRS + xs*CCS;
        const float4* prow = (const float4*)prv + (size_t)((b*HH + y0 + r)*WW + xb + xs)*32 + cc*8;

        #pragma unroll 2
        for (int c4 = 0; c4 < 8; c4++) {
            float4 nv[12];
            #pragma unroll
            for (int m = 0; m < 12; m++)
                nv[m] = *(const float4*)(nbase + m*CCS + c4*4);
            #pragma unroll
            for (int i = 0; i < 4; i++) {
                float4 p = prow[i*32 + c4];
                #pragma unroll
                for (int dj = 0; dj < 9; dj++) {
                    float4 nn = nv[i + dj];
                    float s = acc[i*9+dj];
                    s = fmaf(p.x, nn.x, s); s = fmaf(p.y, nn.y, s);
                    s = fmaf(p.z, nn.z, s); s = fmaf(p.w, nn.w, s);
                    acc[i*9+dj] = s;
                }
            }
        }
    }

    const float inv = 1.0f / 128.0f;
    #pragma unroll
    for (int i = 0; i < 4; i++) {
        size_t base = (size_t)((b*HH + y0 + r)*WW + xb + xs + i)*96 + di*9;
        #pragma unroll
        for (int dj = 0; dj < 9; dj++)
            cost[base + dj] = acc[i*9+dj] * inv;
    }
}

// ================= fused sep-conv layer (mma.sync tf32, pipelined) =================
// 256 threads (8 warps), tile = 16x8 = 128 px (M=128). K-chunks of 32 channels.
// Per chunk: STS prefetched halo + direct B/dw load -> sync -> depthwise -> prefetch
// next halo -> sync -> MMA (double-buffered B, permuted for LDS.128 fragments).
// L0M: 3-source input (chunks 0-3 prv, 4-7 nxt, 8-10 cost[96]).
template<int CIN, int CINB, int COUT, bool L0M>
__global__ void __launch_bounds__(256, 2)
layer_mma(const float* __restrict__ in, const float* __restrict__ in2,
          const float* __restrict__ inc, const float* __restrict__ dww,
          const float* __restrict__ pw, const float* __restrict__ bias,
          float* __restrict__ out)
{
    constexpr int KCH  = CINB / 32;
    constexpr int NT   = COUT / 8;
    constexpr int BSTP = 8*NT + 4;       // permuted B row stride (words)
    constexpr int BBUF = 32 * BSTP;

    extern __shared__ __align__(16) float smf[];
    float*    sdw   = smf;                         // 288
    float*    sbias = smf + 288;                   // 128
    float*    halo  = smf + 416;                   // 5760
    uint32_t* dwt   = (uint32_t*)(smf + 6176);     // 128*36 = 4608
    uint32_t* Bsm   = (uint32_t*)(smf + 10784);    // 2*BBUF

    const int b  = blockIdx.z;
    const int ty = blockIdx.y * 16;
    const int tx = blockIdx.x * 8;
    const int tid = threadIdx.x;
    const int lane = tid & 31;
    const int wid  = tid >> 5;
    const int kq  = lane & 3;
    const int rr  = lane >> 2;

    if (tid < COUT) sbias[tid] = bias[tid];

    // halo geometry for this thread's 6 prefetch slots
    const int pc4 = tid & 7;

    float acc[NT][4];
    #pragma unroll
    for (int n = 0; n < NT; n++)
        #pragma unroll
        for (int j = 0; j < 4; j++) acc[n][j] = 0.f;

    uint4 ph[6];

    // ---- prefetch halo chunk 0 ----
    {
        const float4* src; int cof, strd;
        if constexpr (L0M) { src = (const float4*)in; cof = 0; strd = 32; }
        else               { src = (const float4*)in; cof = 0; strd = CINB/4; }
        #pragma unroll
        for (int s = 0; s < 6; s++) {
            int idx = tid + s*256;
            int p = idx >> 3;
            int hy = p / 10, hx = p - hy*10;
            int gy = ty - 1 + hy, gx = tx - 1 + hx;
            float4 v = make_float4(0.f,0.f,0.f,0.f);
            if (idx < 1440 && gy >= 0 && gy < HH && gx >= 0 && gx < WW)
                v = src[(size_t)((b*HH+gy)*WW+gx)*strd + cof + pc4];
            ph[s] = *(uint4*)&v;
        }
    }

    for (int kc = 0; kc < KCH; kc++) {
        const int k0 = kc * 32;
        uint32_t* Bb = Bsm + (kc & 1) * BBUF;

        // ---- STS prefetched halo ----
        #pragma unroll
        for (int s = 0; s < 6; s++) {
            int idx = tid + s*256;
            if (idx < 1440)
                *(uint4*)(halo + (idx>>3)*32 + pc4*4) = ph[s];
        }
        // ---- B chunk [32][COUT] -> permuted tf32 smem (direct) ----
        #pragma unroll
        for (int s = 0; s < COUT/8; s++) {
            int j = tid + s*256;
            int kk = j / COUT, co = j - kk*COUT;
            int cb = k0 + kk;
            int corig = L0M ? (cb < 256 ? cb + 81 : cb - 256) : cb;
            bool valid = L0M ? (cb < 337) : true;
            float w = valid ? pw[(size_t)corig*COUT + co] : 0.f;
            Bb[kk*BSTP + (co & 7)*NT + (co >> 3)] = f2tf32(w);
        }
        // ---- depthwise weights chunk [9][32] (direct) ----
        #pragma unroll
        for (int s = 0; s < 2; s++) {
            int j = tid + s*256;
            if (j < 288) {
                int t = j >> 5, c = j & 31;
                int cb = k0 + c;
                int corig = L0M ? (cb < 256 ? cb + 81 : cb - 256) : cb;
                bool valid = L0M ? (cb < 337) : true;
                sdw[j] = valid ? dww[t*CIN + corig] : 0.f;
            }
        }
        __syncthreads();   // [A] smem inputs ready

        // ---- depthwise 3x3 -> dwt[px][36] (tf32 bits) ----
        #pragma unroll
        for (int s = 0; s < 4; s++) {
            int task = tid + s*256;
            int c4 = task & 7, px = task >> 3;
            int y = px >> 3, x = px & 7;
            float4 v = make_float4(0.f,0.f,0.f,0.f);
            #pragma unroll
            for (int t = 0; t < 9; t++) {
                int hp = (y + t/3)*10 + (x + t%3);
                float4 h = *(const float4*)(halo + hp*32 + c4*4);
                float4 w = *(const float4*)(sdw  + t*32  + c4*4);
                v.x = fmaf(w.x, h.x, v.x);
                v.y = fmaf(w.y, h.y, v.y);
                v.z = fmaf(w.z, h.z, v.z);
                v.w = fmaf(w.w, h.w, v.w);
            }
            uint4 tv;
            tv.x = f2tf32(v.x); tv.y = f2tf32(v.y);
            tv.z = f2tf32(v.z); tv.w = f2tf32(v.w);
            *(uint4*)(dwt + px*36 + c4*4) = tv;
        }

        // ---- prefetch halo for chunk kc+1 (hidden behind MMA) ----
        if (kc + 1 < KCH) {
            const int kn = kc + 1;
            const float4* src; int cof, strd;
            if constexpr (L0M) {
                if (kn < 4)      { src = (const float4*)in;  cof = kn*8;      strd = 32; }
                else if (kn < 8) { src = (const float4*)in2; cof = (kn-4)*8;  strd = 32; }
                else             { src = (const float4*)inc; cof = (kn-8)*8;  strd = 24; }
            } else {
                src = (const float4*)in; cof = kn*8; strd = CINB/4;
            }
            #pragma unroll
            for (int s = 0; s < 6; s++) {
                int idx = tid + s*256;
                int p = idx >> 3;
                int hy = p / 10, hx = p - hy*10;
                int gy = ty - 1 + hy, gx = tx - 1 + hx;
                float4 v = make_float4(0.f,0.f,0.f,0.f);
                if (idx < 1440 && gy >= 0 && gy < HH && gx >= 0 && gx < WW)
                    v = src[(size_t)((b*HH+gy)*WW+gx)*strd + cof + pc4];
                ph[s] = *(uint4*)&v;
            }
        }
        __syncthreads();   // [B] dwt ready

        // ---- MMA: 4 k-blocks of 8, B fragments via LDS.128 ----
        const uint32_t* arow0 = dwt + (wid*16 + rr)*36;
        const uint32_t* arow1 = arow0 + 8*36;
        #pragma unroll
        for (int kb = 0; kb < 4; kb++) {
            const int kof = kb*8 + kq;
            uint32_t a0 = arow0[kof];
            uint32_t a1 = arow1[kof];
            uint32_t a2 = arow0[kof + 4];
            uint32_t a3 = arow1[kof + 4];
            const uint4* b0p = (const uint4*)(Bb + kof*BSTP + rr*NT);
            const uint4* b1p = (const uint4*)(Bb + (kof+4)*BSTP + rr*NT);
            #pragma unroll
            for (int ng = 0; ng < NT/4; ng++) {
                uint4 b0 = b0p[ng];
                uint4 b1 = b1p[ng];
                mma_tf32(acc[ng*4+0], a0,a1,a2,a3, b0.x, b1.x);
                mma_tf32(acc[ng*4+1], a0,a1,a2,a3, b0.y, b1.y);
                mma_tf32(acc[ng*4+2], a0,a1,a2,a3, b0.z, b1.z);
                mma_tf32(acc[ng*4+3], a0,a1,a2,a3, b0.w, b1.w);
            }
        }
    }

    // ---- epilogue: bias + mish, float2 stores ----
    const int px0 = wid*16 + rr;
    const int px1 = px0 + 8;
    const int y0 = ty + (px0 >> 3), x0c = tx + (px0 & 7);
    const int y1 = ty + (px1 >> 3), x1c = tx + (px1 & 7);
    float* op0 = out + (size_t)((b*HH + y0)*WW + x0c)*COUT;
    float* op1 = out + (size_t)((b*HH + y1)*WW + x1c)*COUT;

    #pragma unroll
    for (int nt = 0; nt < NT; nt++) {
        int ch = nt*8 + kq*2;
        float bb0 = sbias[ch], bb1 = sbias[ch+1];
        float2 r0, r1;
        r0.x = mish_f(acc[nt][0] + bb0);
        r0.y = mish_f(acc[nt][1] + bb1);
        r1.x = mish_f(acc[nt][2] + bb0);
        r1.y = mish_f(acc[nt][3] + bb1);
        *(float2*)(op0 + ch) = r0;
        *(float2*)(op1 + ch) = r1;
    }
}

// ================= final flow head (32 -> 2) =================
__global__ void layer5_kernel(const float* __restrict__ in,
                              const float* __restrict__ dww,
                              const float* __restrict__ pw,
                              float* __restrict__ out)
{
    __shared__ __align__(16) float halo[180*36];
    __shared__ __align__(16) float wsm[288 + 64];

    const int b  = blockIdx.z;
    const int ty = blockIdx.y * 16;
    const int tx = blockIdx.x * 8;
    const int tid = threadIdx.x;

    for (int j = tid; j < 288; j += 128) wsm[j] = dww[j];
    if (tid < 64) wsm[288 + tid] = pw[tid];

    for (int idx = tid; idx < 1440; idx += 128) {
        int c4 = idx & 7, p = idx >> 3;
        int hy = p / 10, hx = p - hy*10;
        int gy = ty - 1 + hy, gx = tx - 1 + hx;
        float4 v = make_float4(0.f,0.f,0.f,0.f);
        if (gy >= 0 && gy < HH && gx >= 0 && gx < WW)
            v = ((const float4*)in)[(size_t)((b*HH+gy)*WW+gx)*8 + c4];
        *(float4*)(halo + p*36 + c4*4) = v;
    }
    __syncthreads();

    int y = tid >> 3, x = tid & 7;
    float dwv[32];
    #pragma unroll
    for (int c = 0; c < 32; c++) dwv[c] = 0.f;

    #pragma unroll
    for (int t = 0; t < 9; t++) {
        int hp = ((y + t/3)*10 + (x + t%3))*36;
        #pragma unroll
        for (int c4 = 0; c4 < 8; c4++) {
            float4 h = *(const float4*)(halo + hp + c4*4);
            float4 w = *(const float4*)(wsm + t*32 + c4*4);
            dwv[c4*4+0] = fmaf(w.x, h.x, dwv[c4*4+0]);
            dwv[c4*4+1] = fmaf(w.y, h.y, dwv[c4*4+1]);
            dwv[c4*4+2] = fmaf(w.z, h.z, dwv[c4*4+2]);
            dwv[c4*4+3] = fmaf(w.w, h.w, dwv[c4*4+3]);
        }
    }

    float o0 = 0.f, o1 = 0.f;
    #pragma unroll
    for (int c = 0; c < 32; c++) {
        o0 = fmaf(dwv[c], wsm[288 + c*2 + 0], o0);
        o1 = fmaf(dwv[c], wsm[288 + c*2 + 1], o1);
    }
    int pix = (b*HH + ty + y)*WW + tx + x;
    float2 r; r.x = o0; r.y = o1;
    *(float2*)(out + (size_t)pix*2) = r;
}

// ================= host launch =================
extern "C" void kernel_launch(void* const* d_in, const int* in_sizes, int n_in,
                              void* d_out, int out_size)
{
    const float* prv = (const float*)d_in[0];
    const float* nxt = (const float*)d_in[1];
    const float* dw0 = (const float*)d_in[2];
    const float* pw0 = (const float*)d_in[3];
    const float* b0  = (const float*)d_in[4];
    const float* dw1 = (const float*)d_in[5];
    const float* pw1 = (const float*)d_in[6];
    const float* b1  = (const float*)d_in[7];
    const float* dw2 = (const float*)d_in[8];
    const float* pw2 = (const float*)d_in[9];
    const float* b2  = (const float*)d_in[10];
    const float* dw3 = (const float*)d_in[11];
    const float* pw3 = (const float*)d_in[12];
    const float* b3  = (const float*)d_in[13];
    const float* dw4 = (const float*)d_in[14];
    const float* pw4 = (const float*)d_in[15];
    const float* b4  = (const float*)d_in[16];
    const float* dw5 = (const float*)d_in[17];
    const float* pw5 = (const float*)d_in[18];
    float* out = (float*)d_out;

    float *cost, *bufA, *bufB;
    cudaGetSymbolAddress((void**)&cost, g_cost);
    cudaGetSymbolAddress((void**)&bufA, g_bufA);
    cudaGetSymbolAddress((void**)&bufB, g_bufB);

    const int SC = 24*CRS*4;
    // layer smem bytes: (10784 + 2*32*(8*NT+4)) * 4
    const int SL128 = (10784 + 64*132) * 4;  // 76928
    const int SL96  = (10784 + 64*100) * 4;  // 68736
    const int SL64  = (10784 + 64*68 ) * 4;  // 60544
    const int SL32  = (10784 + 64*36 ) * 4;  // 52352

    cudaFuncSetAttribute(cost_kernel, cudaFuncAttributeMaxDynamicSharedMemorySize, SC);
    cudaFuncSetAttribute((const void*)layer_mma<337,352,128,true >, cudaFuncAttributeMaxDynamicSharedMemorySize, SL128);
    cudaFuncSetAttribute((const void*)layer_mma<128,128,128,false>, cudaFuncAttributeMaxDynamicSharedMemorySize, SL128);
    cudaFuncSetAttribute((const void*)layer_mma<128,128, 96,false>, cudaFuncAttributeMaxDynamicSharedMemorySize, SL96);
    cudaFuncSetAttribute((const void*)layer_mma< 96, 96, 64,false>, cudaFuncAttributeMaxDynamicSharedMemorySize, SL64);
    cudaFuncSetAttribute((const void*)layer_mma< 64, 64, 32,false>, cudaFuncAttributeMaxDynamicSharedMemorySize, SL32);

    dim3 cgrid(16, 8, BATCH);
    cost_kernel<<<cgrid, 288, SC>>>(prv, nxt, cost);

    dim3 lgrid(16, 8, BATCH);
    layer_mma<337,352,128,true ><<<lgrid, 256, SL128>>>(prv,  nxt, cost, dw0, pw0, b0, bufA);
    layer_mma<128,128,128,false><<<lgrid, 256, SL128>>>(bufA, nullptr, nullptr, dw1, pw1, b1, bufB);
    layer_mma<128,128, 96,false><<<lgrid, 256, SL96 >>>(bufB, nullptr, nullptr, dw2, pw2, b2, bufA);
    layer_mma< 96, 96, 64,false><<<lgrid, 256, SL64 >>>(bufA, nullptr, nullptr, dw3, pw3, b3, bufB);
    layer_mma< 64, 64, 32,false><<<lgrid, 256, SL32 >>>(bufB, nullptr, nullptr, dw4, pw4, b4, bufA);

    layer5_kernel<<<lgrid, 128>>>(bufA, dw5, pw5, out);
}

// round 6
// speedup vs baseline: 6.9179x; 1.4208x over previous
#include <cuda_runtime.h>
#include <math.h>
#include <stdint.h>

#define HH 128
#define WW 128
#define BATCH 8
#define NPIX (BATCH*HH*WW)

// cost buffer: 96 channels per pixel (81 used, pad zero — never written, zero-init)
__device__ float g_cost[(size_t)NPIX*96];
__device__ float g_bufA[(size_t)NPIX*128];
__device__ float g_bufB[(size_t)NPIX*128];

__device__ __forceinline__ float mish_f(float v) {
    if (v > 20.f) return v;
    float u = __expf(v);
    float w = u * (u + 2.f);
    return v * __fdividef(w, w + 2.f);
}

__device__ __forceinline__ uint32_t f2tf32(float x) {
    uint32_t r;
    asm("cvt.rna.tf32.f32 %0, %1;" : "=r"(r) : "f"(x));
    return r;
}

__device__ __forceinline__ void mma_tf32(float acc[4],
                                         uint32_t a0, uint32_t a1, uint32_t a2, uint32_t a3,
                                         uint32_t b0, uint32_t b1) {
    asm volatile(
        "mma.sync.aligned.m16n8k8.row.col.f32.tf32.tf32.f32 "
        "{%0,%1,%2,%3}, {%4,%5,%6,%7}, {%8,%9}, {%0,%1,%2,%3};"
        : "+f"(acc[0]), "+f"(acc[1]), "+f"(acc[2]), "+f"(acc[3])
        : "r"(a0), "r"(a1), "r"(a2), "r"(a3), "r"(b0), "r"(b1));
}

// ================= cost volume =================
#define CCS 36
#define CRS 580
__global__ void __launch_bounds__(288, 2)
cost_kernel(const float* __restrict__ prv, const float* __restrict__ nxt,
            float* __restrict__ cost)
{
    extern __shared__ __align__(16) float sm[];
    const int b  = blockIdx.z;
    const int y0 = blockIdx.y * 16;
    const int xb = blockIdx.x * 8;
    const int tid = threadIdx.x;
    const int r  = tid / 18;
    const int q  = (tid % 18) / 9;
    const int di = tid % 9;
    const int xs = q * 4;

    float acc[36];
    #pragma unroll
    for (int k = 0; k < 36; k++) acc[k] = 0.f;

    for (int cc = 0; cc < 4; cc++) {
        if (cc) __syncthreads();
        for (int idx = tid; idx < 3072; idx += 288) {
            int c4 = idx & 7, col = (idx >> 3) & 15, row = idx >> 7;
            int gy = y0 - 4 + row, gx = xb - 4 + col;
            float4 v = make_float4(0.f,0.f,0.f,0.f);
            if (gy >= 0 && gy < HH && gx >= 0 && gx < WW)
                v = ((const float4*)nxt)[((b*HH+gy)*WW+gx)*32 + cc*8 + c4];
            *(float4*)(sm + row*CRS + col*CCS + c4*4) = v;
        }
        __syncthreads();

        const float* nbase = sm + (r + di)*CRS + xs*CCS;
        const float4* prow = (const float4*)prv + (size_t)((b*HH + y0 + r)*WW + xb + xs)*32 + cc*8;

        #pragma unroll 2
        for (int c4 = 0; c4 < 8; c4++) {
            float4 nv[12];
            #pragma unroll
            for (int m = 0; m < 12; m++)
                nv[m] = *(const float4*)(nbase + m*CCS + c4*4);
            #pragma unroll
            for (int i = 0; i < 4; i++) {
                float4 p = prow[i*32 + c4];
                #pragma unroll
                for (int dj = 0; dj < 9; dj++) {
                    float4 nn = nv[i + dj];
                    float s = acc[i*9+dj];
                    s = fmaf(p.x, nn.x, s); s = fmaf(p.y, nn.y, s);
                    s = fmaf(p.z, nn.z, s); s = fmaf(p.w, nn.w, s);
                    acc[i*9+dj] = s;
                }
            }
        }
    }

    const float inv = 1.0f / 128.0f;
    #pragma unroll
    for (int i = 0; i < 4; i++) {
        size_t base = (size_t)((b*HH + y0 + r)*WW + xb + xs + i)*96 + di*9;
        #pragma unroll
        for (int dj = 0; dj < 9; dj++)
            cost[base + dj] = acc[i*9+dj] * inv;
    }
}

// ================= fused sep-conv layer (mma.sync tf32, cp.async pipelined) =================
// 256 threads (8 warps), tile = 16x8 = 128 px (M=128). K-chunks of 32 channels.
// Double-buffered halo via cp.async (zero-fill OOB); row-based depthwise with
// horizontal register reuse; permuted double-buffered B for LDS.128 MMA fragments.
template<int CIN, int CINB, int COUT, bool L0M>
__global__ void __launch_bounds__(256, 2)
layer_mma(const float* __restrict__ in, const float* __restrict__ in2,
          const float* __restrict__ inc, const float* __restrict__ dww,
          const float* __restrict__ pw, const float* __restrict__ bias,
          float* __restrict__ out)
{
    constexpr int KCH  = CINB / 32;
    constexpr int NT   = COUT / 8;
    constexpr int BSTP = 8*NT + 4;       // permuted B row stride (words)
    constexpr int BBUF = 32 * BSTP;

    extern __shared__ __align__(16) float smf[];
    float*    sdw   = smf;                          // 288
    float*    sbias = smf + 288;                    // 128
    float*    halo  = smf + 416;                    // 2 x 5760
    uint32_t* dwt   = (uint32_t*)(smf + 11936);     // 128*36 = 4608
    uint32_t* Bsm   = (uint32_t*)(smf + 16544);     // 2*BBUF

    const int b  = blockIdx.z;
    const int ty = blockIdx.y * 16;
    const int tx = blockIdx.x * 8;
    const int tid = threadIdx.x;
    const int lane = tid & 31;
    const int wid  = tid >> 5;
    const int kq  = lane & 3;
    const int rr  = lane >> 2;
    const int pc4 = tid & 7;

    if (tid < COUT) sbias[tid] = bias[tid];

    // ---- hoisted halo prefetch geometry (chunk-invariant) ----
    int      hoff[6];
    int      hsz [6];
    uint32_t hdst[6];
    const uint32_t halo_sa = (uint32_t)__cvta_generic_to_shared(halo);
    #pragma unroll
    for (int s = 0; s < 6; s++) {
        int idx = tid + s*256;
        int p = idx >> 3;
        int hy = p / 10, hx = p - hy*10;
        int gy = ty - 1 + hy, gx = tx - 1 + hx;
        bool v = (idx < 1440) && gy >= 0 && gy < HH && gx >= 0 && gx < WW;
        int gyc = min(max(gy, 0), HH-1), gxc = min(max(gx, 0), WW-1);
        hoff[s] = (b*HH + gyc)*WW + gxc;
        hsz [s] = v ? 16 : 0;
        hdst[s] = halo_sa + (uint32_t)p*128 + (uint32_t)pc4*16;
    }

    auto issue_prefetch = [&](int kn, uint32_t bufb) {
        const float4* src; int cof, strd;
        if constexpr (L0M) {
            if (kn < 4)      { src = (const float4*)in;  cof = kn*8;     strd = 32; }
            else if (kn < 8) { src = (const float4*)in2; cof = (kn-4)*8; strd = 32; }
            else             { src = (const float4*)inc; cof = (kn-8)*8; strd = 24; }
        } else {
            src = (const float4*)in; cof = kn*8; strd = CINB/4;
        }
        #pragma unroll
        for (int s = 0; s < 6; s++) {
            if (tid + s*256 < 1440) {
                const void* p = (const void*)(src + (size_t)hoff[s]*strd + cof + pc4);
                asm volatile("cp.async.cg.shared.global [%0], [%1], 16, %2;"
                             :: "r"(hdst[s] + bufb), "l"(p), "r"(hsz[s]) : "memory");
            }
        }
        asm volatile("cp.async.commit_group;" ::: "memory");
    };

    float acc[NT][4];
    #pragma unroll
    for (int n = 0; n < NT; n++)
        #pragma unroll
        for (int j = 0; j < 4; j++) acc[n][j] = 0.f;

    issue_prefetch(0, 0);

    // depthwise task geometry: 4 adjacent px in a row, one channel quad
    const int dr  = tid >> 4;               // row 0..15
    const int dxh = ((tid >> 3) & 1) * 4;   // x-half 0 or 4

    for (int kc = 0; kc < KCH; kc++) {
        const int k0 = kc * 32;
        uint32_t* Bb = Bsm + (kc & 1) * BBUF;

        // ---- B chunk [32][COUT] -> permuted tf32 smem ----
        #pragma unroll
        for (int s = 0; s < COUT/8; s++) {
            int j = tid + s*256;
            int kk = j / COUT, co = j - kk*COUT;
            int cb = k0 + kk;
            int corig = L0M ? (cb < 256 ? cb + 81 : cb - 256) : cb;
            bool valid = L0M ? (cb < 337) : true;
            float w = valid ? pw[(size_t)corig*COUT + co] : 0.f;
            Bb[kk*BSTP + (co & 7)*NT + (co >> 3)] = f2tf32(w);
        }
        // ---- depthwise weights chunk [9][32] ----
        #pragma unroll
        for (int s = 0; s < 2; s++) {
            int j = tid + s*256;
            if (j < 288) {
                int t = j >> 5, c = j & 31;
                int cb = k0 + c;
                int corig = L0M ? (cb < 256 ? cb + 81 : cb - 256) : cb;
                bool valid = L0M ? (cb < 337) : true;
                sdw[j] = valid ? dww[t*CIN + corig] : 0.f;
            }
        }
        asm volatile("cp.async.wait_group 0;" ::: "memory");
        __syncthreads();   // [A] halo + B + dw ready

        // ---- depthwise 3x3: 4 adjacent px, one c4 quad, row-window reuse ----
        {
            const float* hb = halo + (kc & 1) * 5760;
            float4 o0 = make_float4(0.f,0.f,0.f,0.f);
            float4 o1 = o0, o2 = o0, o3 = o0;
            #pragma unroll
            for (int tyy = 0; tyy < 3; tyy++) {
                const float* hr = hb + ((dr + tyy)*10 + dxh)*32 + pc4*4;
                float4 h0 = *(const float4*)(hr + 0*32);
                float4 h1 = *(const float4*)(hr + 1*32);
                float4 h2 = *(const float4*)(hr + 2*32);
                float4 h3 = *(const float4*)(hr + 3*32);
                float4 h4 = *(const float4*)(hr + 4*32);
                float4 h5 = *(const float4*)(hr + 5*32);
                float4 w0 = *(const float4*)(sdw + (tyy*3+0)*32 + pc4*4);
                float4 w1 = *(const float4*)(sdw + (tyy*3+1)*32 + pc4*4);
                float4 w2 = *(const float4*)(sdw + (tyy*3+2)*32 + pc4*4);
                #define DWACC(o, a, b, c) \
                    o.x = fmaf(w0.x, a.x, o.x); o.y = fmaf(w0.y, a.y, o.y); \
                    o.z = fmaf(w0.z, a.z, o.z); o.w = fmaf(w0.w, a.w, o.w); \
                    o.x = fmaf(w1.x, b.x, o.x); o.y = fmaf(w1.y, b.y, o.y); \
                    o.z = fmaf(w1.z, b.z, o.z); o.w = fmaf(w1.w, b.w, o.w); \
                    o.x = fmaf(w2.x, c.x, o.x); o.y = fmaf(w2.y, c.y, o.y); \
                    o.z = fmaf(w2.z, c.z, o.z); o.w = fmaf(w2.w, c.w, o.w);
                DWACC(o0, h0, h1, h2)
                DWACC(o1, h1, h2, h3)
                DWACC(o2, h2, h3, h4)
                DWACC(o3, h3, h4, h5)
                #undef DWACC
            }
            const int pxb = dr*8 + dxh;
            uint4 t0, t1, t2, t3;
            t0.x=f2tf32(o0.x); t0.y=f2tf32(o0.y); t0.z=f2tf32(o0.z); t0.w=f2tf32(o0.w);
            t1.x=f2tf32(o1.x); t1.y=f2tf32(o1.y); t1.z=f2tf32(o1.z); t1.w=f2tf32(o1.w);
            t2.x=f2tf32(o2.x); t2.y=f2tf32(o2.y); t2.z=f2tf32(o2.z); t2.w=f2tf32(o2.w);
            t3.x=f2tf32(o3.x); t3.y=f2tf32(o3.y); t3.z=f2tf32(o3.z); t3.w=f2tf32(o3.w);
            *(uint4*)(dwt + (pxb+0)*36 + pc4*4) = t0;
            *(uint4*)(dwt + (pxb+1)*36 + pc4*4) = t1;
            *(uint4*)(dwt + (pxb+2)*36 + pc4*4) = t2;
            *(uint4*)(dwt + (pxb+3)*36 + pc4*4) = t3;
        }

        // ---- prefetch halo for chunk kc+1 (async, hidden behind MMA) ----
        if (kc + 1 < KCH)
            issue_prefetch(kc + 1, (uint32_t)(((kc + 1) & 1) * 23040));
        __syncthreads();   // [B] dwt ready

        // ---- MMA: 4 k-blocks of 8, B fragments via LDS.128 ----
        const uint32_t* arow0 = dwt + (wid*16 + rr)*36;
        const uint32_t* arow1 = arow0 + 8*36;
        #pragma unroll
        for (int kb = 0; kb < 4; kb++) {
            const int kof = kb*8 + kq;
            uint32_t a0 = arow0[kof];
            uint32_t a1 = arow1[kof];
            uint32_t a2 = arow0[kof + 4];
            uint32_t a3 = arow1[kof + 4];
            const uint4* b0p = (const uint4*)(Bb + kof*BSTP + rr*NT);
            const uint4* b1p = (const uint4*)(Bb + (kof+4)*BSTP + rr*NT);
            #pragma unroll
            for (int ng = 0; ng < NT/4; ng++) {
                uint4 b0 = b0p[ng];
                uint4 b1 = b1p[ng];
                mma_tf32(acc[ng*4+0], a0,a1,a2,a3, b0.x, b1.x);
                mma_tf32(acc[ng*4+1], a0,a1,a2,a3, b0.y, b1.y);
                mma_tf32(acc[ng*4+2], a0,a1,a2,a3, b0.z, b1.z);
                mma_tf32(acc[ng*4+3], a0,a1,a2,a3, b0.w, b1.w);
            }
        }
    }

    // ---- epilogue: bias + mish, float2 stores ----
    const int px0 = wid*16 + rr;
    const int px1 = px0 + 8;
    const int y0 = ty + (px0 >> 3), x0c = tx + (px0 & 7);
    const int y1 = ty + (px1 >> 3), x1c = tx + (px1 & 7);
    float* op0 = out + (size_t)((b*HH + y0)*WW + x0c)*COUT;
    float* op1 = out + (size_t)((b*HH + y1)*WW + x1c)*COUT;

    #pragma unroll
    for (int nt = 0; nt < NT; nt++) {
        int ch = nt*8 + kq*2;
        float bb0 = sbias[ch], bb1 = sbias[ch+1];
        float2 r0, r1;
        r0.x = mish_f(acc[nt][0] + bb0);
        r0.y = mish_f(acc[nt][1] + bb1);
        r1.x = mish_f(acc[nt][2] + bb0);
        r1.y = mish_f(acc[nt][3] + bb1);
        *(float2*)(op0 + ch) = r0;
        *(float2*)(op1 + ch) = r1;
    }
}

// ================= final flow head (32 -> 2) =================
__global__ void layer5_kernel(const float* __restrict__ in,
                              const float* __restrict__ dww,
                              const float* __restrict__ pw,
                              float* __restrict__ out)
{
    __shared__ __align__(16) float halo[180*36];
    __shared__ __align__(16) float wsm[288 + 64];

    const int b  = blockIdx.z;
    const int ty = blockIdx.y * 16;
    const int tx = blockIdx.x * 8;
    const int tid = threadIdx.x;

    for (int j = tid; j < 288; j += 128) wsm[j] = dww[j];
    if (tid < 64) wsm[288 + tid] = pw[tid];

    for (int idx = tid; idx < 1440; idx += 128) {
        int c4 = idx & 7, p = idx >> 3;
        int hy = p / 10, hx = p - hy*10;
        int gy = ty - 1 + hy, gx = tx - 1 + hx;
        float4 v = make_float4(0.f,0.f,0.f,0.f);
        if (gy >= 0 && gy < HH && gx >= 0 && gx < WW)
            v = ((const float4*)in)[(size_t)((b*HH+gy)*WW+gx)*8 + c4];
        *(float4*)(halo + p*36 + c4*4) = v;
    }
    __syncthreads();

    int y = tid >> 3, x = tid & 7;
    float dwv[32];
    #pragma unroll
    for (int c = 0; c < 32; c++) dwv[c] = 0.f;

    #pragma unroll
    for (int t = 0; t < 9; t++) {
        int hp = ((y + t/3)*10 + (x + t%3))*36;
        #pragma unroll
        for (int c4 = 0; c4 < 8; c4++) {
            float4 h = *(const float4*)(halo + hp + c4*4);
            float4 w = *(const float4*)(wsm + t*32 + c4*4);
            dwv[c4*4+0] = fmaf(w.x, h.x, dwv[c4*4+0]);
            dwv[c4*4+1] = fmaf(w.y, h.y, dwv[c4*4+1]);
            dwv[c4*4+2] = fmaf(w.z, h.z, dwv[c4*4+2]);
            dwv[c4*4+3] = fmaf(w.w, h.w, dwv[c4*4+3]);
        }
    }

    float o0 = 0.f, o1 = 0.f;
    #pragma unroll
    for (int c = 0; c < 32; c++) {
        o0 = fmaf(dwv[c], wsm[288 + c*2 + 0], o0);
        o1 = fmaf(dwv[c], wsm[288 + c*2 + 1], o1);
    }
    int pix = (b*HH + ty + y)*WW + tx + x;
    float2 r; r.x = o0; r.y = o1;
    *(float2*)(out + (size_t)pix*2) = r;
}

// ================= host launch =================
extern "C" void kernel_launch(void* const* d_in, const int* in_sizes, int n_in,
                              void* d_out, int out_size)
{
    const float* prv = (const float*)d_in[0];
    const float* nxt = (const float*)d_in[1];
    const float* dw0 = (const float*)d_in[2];
    const float* pw0 = (const float*)d_in[3];
    const float* b0  = (const float*)d_in[4];
    const float* dw1 = (const float*)d_in[5];
    const float* pw1 = (const float*)d_in[6];
    const float* b1  = (const float*)d_in[7];
    const float* dw2 = (const float*)d_in[8];
    const float* pw2 = (const float*)d_in[9];
    const float* b2  = (const float*)d_in[10];
    const float* dw3 = (const float*)d_in[11];
    const float* pw3 = (const float*)d_in[12];
    const float* b3  = (const float*)d_in[13];
    const float* dw4 = (const float*)d_in[14];
    const float* pw4 = (const float*)d_in[15];
    const float* b4  = (const float*)d_in[16];
    const float* dw5 = (const float*)d_in[17];
    const float* pw5 = (const float*)d_in[18];
    float* out = (float*)d_out;

    float *cost, *bufA, *bufB;
    cudaGetSymbolAddress((void**)&cost, g_cost);
    cudaGetSymbolAddress((void**)&bufA, g_bufA);
    cudaGetSymbolAddress((void**)&bufB, g_bufB);

    const int SC = 24*CRS*4;
    // layer smem bytes: (16544 + 2*32*(8*NT+4)) * 4
    const int SL128 = (16544 + 64*132) * 4;  // 99968
    const int SL96  = (16544 + 64*100) * 4;  // 91776
    const int SL64  = (16544 + 64*68 ) * 4;  // 83584
    const int SL32  = (16544 + 64*36 ) * 4;  // 75392

    cudaFuncSetAttribute(cost_kernel, cudaFuncAttributeMaxDynamicSharedMemorySize, SC);
    cudaFuncSetAttribute((const void*)layer_mma<337,352,128,true >, cudaFuncAttributeMaxDynamicSharedMemorySize, SL128);
    cudaFuncSetAttribute((const void*)layer_mma<128,128,128,false>, cudaFuncAttributeMaxDynamicSharedMemorySize, SL128);
    cudaFuncSetAttribute((const void*)layer_mma<128,128, 96,false>, cudaFuncAttributeMaxDynamicSharedMemorySize, SL96);
    cudaFuncSetAttribute((const void*)layer_mma< 96, 96, 64,false>, cudaFuncAttributeMaxDynamicSharedMemorySize, SL64);
    cudaFuncSetAttribute((const void*)layer_mma< 64, 64, 32,false>, cudaFuncAttributeMaxDynamicSharedMemorySize, SL32);

    dim3 cgrid(16, 8, BATCH);
    cost_kernel<<<cgrid, 288, SC>>>(prv, nxt, cost);

    dim3 lgrid(16, 8, BATCH);
    layer_mma<337,352,128,true ><<<lgrid, 256, SL128>>>(prv,  nxt, cost, dw0, pw0, b0, bufA);
    layer_mma<128,128,128,false><<<lgrid, 256, SL128>>>(bufA, nullptr, nullptr, dw1, pw1, b1, bufB);
    layer_mma<128,128, 96,false><<<lgrid, 256, SL96 >>>(bufB, nullptr, nullptr, dw2, pw2, b2, bufA);
    layer_mma< 96, 96, 64,false><<<lgrid, 256, SL64 >>>(bufA, nullptr, nullptr, dw3, pw3, b3, bufB);
    layer_mma< 64, 64, 32,false><<<lgrid, 256, SL32 >>>(bufB, nullptr, nullptr, dw4, pw4, b4, bufA);

    layer5_kernel<<<lgrid, 128>>>(bufA, dw5, pw5, out);
}